// round 12
// baseline (speedup 1.0000x reference)
#include <cuda_runtime.h>
#include <cuda_bf16.h>
#include <cstdint>

// ============================================================================
// GCN fused layer via warp-level bf16 mma.sync (portable PTX; tcgen05 is
// rejected by the harness's .target sm_103 ptxas pass):
//   support = y @ W                      (GEMM1, 8192x1024x1024, bf16 out)
//   out     = relu(adj @ support / adj_sumrow + b + x)   (GEMM2, 8x 1024^3)
// R12: 512 threads/CTA (16 warps, warp tile 32x32, acc 32 regs) -> 8 warps
//      per SMSP to fill the 58%-idle tensor pipe. R10 stream schedule
//      (forked cvt_adj); R11 half-split reverted (no overlap, neutral).
// ============================================================================

__device__ __nv_bfloat16 g_ybf  [8u * 1024u * 1024u];
__device__ __nv_bfloat16 g_adjbf[8u * 1024u * 1024u];
__device__ __nv_bfloat16 g_wbf  [1024u * 1024u];
__device__ __nv_bfloat16 g_sup  [8u * 1024u * 1024u];

static __device__ __forceinline__ uint32_t smem_u32(const void* p) {
    uint32_t a;
    asm("{ .reg .u64 t; cvta.to.shared.u64 t, %1; cvt.u32.u64 %0, t; }"
        : "=r"(a) : "l"(p));
    return a;
}

// ---- tile geometry ----------------------------------------------------------
#define BM 128
#define BN 128
#define BK 64
#define NSTAGE 3
#define NTHREADS 512
#define LDA_B 144    // A smem row stride bytes (64 bf16 = 128B + 16 pad)
#define LDB_B 272    // B smem row stride bytes (128 bf16 + 8 pad)
#define A_SM_BYTES (BM * LDA_B)                   // 18432
#define B_SM_BYTES (BK * LDB_B)                   // 17408
#define STAGE_BYTES (A_SM_BYTES + B_SM_BYTES)     // 35840
#define BIAS_OFF (NSTAGE * STAGE_BYTES)           // 107520
#define SMEM_TOTAL (BIAS_OFF + 512)               // 108032

// ---- PTX wrappers -----------------------------------------------------------
#define CP_ASYNC_16(saddr, gptr) \
    asm volatile("cp.async.cg.shared.global [%0], [%1], 16;" \
        :: "r"(saddr), "l"(gptr) : "memory")
#define CP_ASYNC_COMMIT() asm volatile("cp.async.commit_group;" ::: "memory")
#define CP_ASYNC_WAIT_1() asm volatile("cp.async.wait_group 1;" ::: "memory")
#define CP_ASYNC_WAIT_0() asm volatile("cp.async.wait_group 0;" ::: "memory")

#define LDMATRIX_X4(r0, r1, r2, r3, addr) \
    asm volatile("ldmatrix.sync.aligned.m8n8.x4.shared.b16 {%0,%1,%2,%3}, [%4];" \
        : "=r"(r0), "=r"(r1), "=r"(r2), "=r"(r3) : "r"(addr))
#define LDMATRIX_X4_T(r0, r1, r2, r3, addr) \
    asm volatile("ldmatrix.sync.aligned.m8n8.x4.trans.shared.b16 {%0,%1,%2,%3}, [%4];" \
        : "=r"(r0), "=r"(r1), "=r"(r2), "=r"(r3) : "r"(addr))

#define MMA_BF16(c, a0, a1, a2, a3, b0, b1) \
    asm volatile("mma.sync.aligned.m16n8k16.row.col.f32.bf16.bf16.f32 " \
        "{%0,%1,%2,%3}, {%4,%5,%6,%7}, {%8,%9}, {%0,%1,%2,%3};" \
        : "+f"((c)[0]), "+f"((c)[1]), "+f"((c)[2]), "+f"((c)[3]) \
        : "r"(a0), "r"(a1), "r"(a2), "r"(a3), "r"(b0), "r"(b1))

static __device__ __forceinline__ uint2 cvt4(float4 v) {
    uint32_t lo = (uint32_t)__bfloat16_as_ushort(__float2bfloat16_rn(v.x))
                | ((uint32_t)__bfloat16_as_ushort(__float2bfloat16_rn(v.y)) << 16);
    uint32_t hi = (uint32_t)__bfloat16_as_ushort(__float2bfloat16_rn(v.z))
                | ((uint32_t)__bfloat16_as_ushort(__float2bfloat16_rn(v.w)) << 16);
    return make_uint2(lo, hi);
}

// ---- f32 -> bf16 conversion for up to two tensors, MLP=2 --------------------
__global__ void cvt_pair_bf16(const float4* __restrict__ p0, uint2* __restrict__ o0, int n0,
                              const float4* __restrict__ p1, uint2* __restrict__ o1, int n1) {
    const int total = n0 + n1;
    const int stride = gridDim.x * blockDim.x;
    int i = blockIdx.x * blockDim.x + threadIdx.x;
    for (; i + stride < total; i += 2 * stride) {
        int idx0 = i, idx1 = i + stride;
        const float4 *in0, *in1;
        uint2 *out0, *out1;
        if (idx0 < n0) { in0 = p0; out0 = o0; } else { idx0 -= n0; in0 = p1; out0 = o1; }
        if (idx1 < n0) { in1 = p0; out1 = o0; } else { idx1 -= n0; in1 = p1; out1 = o1; }
        float4 v0 = __ldcs(in0 + idx0);
        float4 v1 = __ldcs(in1 + idx1);
        __stcs(out0 + idx0, cvt4(v0));
        __stcs(out1 + idx1, cvt4(v1));
    }
    if (i < total) {
        int idx = i;
        const float4* in;
        uint2* out;
        if (idx < n0) { in = p0; out = o0; } else { idx -= n0; in = p1; out = o1; }
        __stcs(out + idx, cvt4(__ldcs(in + idx)));
    }
}

// ---- mma.sync GEMM kernel: 512 threads, 16 warps (4Mx4N), warp tile 32x32 ---
// A: [M,K] bf16 row-major.  B: [K,N] bf16 row-major.
__global__ __launch_bounds__(NTHREADS, 2)
void gcn_mma_kernel(
    const __nv_bfloat16* __restrict__ A,
    const __nv_bfloat16* __restrict__ B,
    void* __restrict__ Cout,
    int M, int N, int K,
    long strideA, long strideB, long strideC,
    const float* __restrict__ sumrow,
    const float* __restrict__ bias,
    const float* __restrict__ xres,
    int do_epi)
{
    extern __shared__ char smem[];
    const uint32_t sb = smem_u32(smem);
    const int tid = threadIdx.x;
    const int wid = tid >> 5;
    const int lane = tid & 31;
    const int bx = blockIdx.x, by = blockIdx.y, bz = blockIdx.z;

    A += (long)bz * strideA + (long)by * BM * K;
    B += (long)bz * strideB + (long)bx * BN;

    if (do_epi && tid < 128)
        ((float*)(smem + BIAS_OFF))[tid] = bias[bx * BN + tid];

    // ---- stage loader: cp.async 16B chunks, 512 threads ---------------------
    // A tile: 128 rows x 8 chunks = 1024 -> 2/thread. B: 64 rows x 16 = 1024 -> 2/thread.
    const int aRow0 = tid >> 3, aC16 = tid & 7;          // A: rows += c*64
    const int bRow0 = tid >> 4, bC16 = tid & 15;         // B: rows += c*32
    auto load_stage = [&](int s, int k0) {
        const uint32_t base = sb + s * STAGE_BYTES;
        #pragma unroll
        for (int c = 0; c < 2; c++) {
            const int row = aRow0 + c * 64;
            const __nv_bfloat16* g = A + (long)row * K + k0 + aC16 * 8;
            CP_ASYNC_16(base + row * LDA_B + aC16 * 16, g);
        }
        #pragma unroll
        for (int c = 0; c < 2; c++) {
            const int row = bRow0 + c * 32;
            const __nv_bfloat16* g = B + (long)(k0 + row) * N + bC16 * 8;
            CP_ASYNC_16(base + A_SM_BYTES + row * LDB_B + bC16 * 16, g);
        }
        CP_ASYNC_COMMIT();
    };

    const int wm = wid >> 2;       // 0..3 -> M offset wm*32
    const int wn = wid & 3;        // 0..3 -> N offset wn*32

    float acc[2][4][4];
    #pragma unroll
    for (int i = 0; i < 2; i++)
        #pragma unroll
        for (int j = 0; j < 4; j++)
            #pragma unroll
            for (int k = 0; k < 4; k++)
                acc[i][j][k] = 0.0f;

    const int a_row_in = lane & 15;
    const int a_koff = (lane >> 4) * 16;
    const int b_grp = lane >> 3, b_in = lane & 7;
    const int b_krow_in = (b_grp & 1) * 8 + b_in;
    const int b_noff = (b_grp >> 1) * 16;

    const int NIT = K / BK;

    // prime 2 stages of the 3-stage ring
    load_stage(0, 0);
    load_stage(1, BK);

    int cur = 0;
    for (int it = 0; it < NIT; ++it) {
        if (it + 1 < NIT) CP_ASYNC_WAIT_1(); else CP_ASYNC_WAIT_0();
        __syncthreads();

        if (it + 2 < NIT) {
            int nxt = cur + 2; if (nxt >= NSTAGE) nxt -= NSTAGE;
            load_stage(nxt, (it + 2) * BK);
        }

        const uint32_t base_a = sb + cur * STAGE_BYTES;
        const uint32_t base_b = base_a + A_SM_BYTES;

        #pragma unroll
        for (int kk = 0; kk < 4; kk++) {    // 4 x k16 phases per BK=64
            uint32_t af[2][4], bfr[2][4];
            #pragma unroll
            for (int mt = 0; mt < 2; mt++) {
                const int row = wm * 32 + mt * 16 + a_row_in;
                const uint32_t ad = base_a + row * LDA_B + kk * 32 + a_koff;
                LDMATRIX_X4(af[mt][0], af[mt][1], af[mt][2], af[mt][3], ad);
            }
            #pragma unroll
            for (int nb = 0; nb < 2; nb++) {
                const int krow = kk * 16 + b_krow_in;
                const uint32_t bd = base_b + krow * LDB_B
                                  + wn * 64 + nb * 32 + b_noff;
                LDMATRIX_X4_T(bfr[nb][0], bfr[nb][1], bfr[nb][2], bfr[nb][3], bd);
            }
            #pragma unroll
            for (int mt = 0; mt < 2; mt++) {
                #pragma unroll
                for (int nt = 0; nt < 4; nt++) {
                    MMA_BF16(acc[mt][nt],
                             af[mt][0], af[mt][1], af[mt][2], af[mt][3],
                             bfr[nt >> 1][(nt & 1) * 2],
                             bfr[nt >> 1][(nt & 1) * 2 + 1]);
                }
            }
        }

        if (++cur >= NSTAGE) cur = 0;
    }

    // ---- epilogue -----------------------------------------------------------
    const int r_in = lane >> 2;
    const int c_in = (lane & 3) * 2;

    if (do_epi) {
        const float* bsm = (const float*)(smem + BIAS_OFF);
        #pragma unroll
        for (int mt = 0; mt < 2; mt++) {
            #pragma unroll
            for (int half = 0; half < 2; half++) {
                const int row = by * BM + wm * 32 + mt * 16 + r_in + half * 8;
                const float inv = 1.0f / sumrow[bz * M + row];
                const long rb = (long)bz * strideC + (long)row * N + bx * BN;
                #pragma unroll
                for (int nt = 0; nt < 4; nt++) {
                    const int col = wn * 32 + nt * 8 + c_in;
                    const float a0 = acc[mt][nt][half * 2 + 0];
                    const float a1 = acc[mt][nt][half * 2 + 1];
                    float2 xv = *(const float2*)(xres + rb + col);
                    float2 o;
                    o.x = fmaxf(a0 * inv + bsm[col + 0] + xv.x, 0.0f);
                    o.y = fmaxf(a1 * inv + bsm[col + 1] + xv.y, 0.0f);
                    *(float2*)((float*)Cout + rb + col) = o;
                }
            }
        }
    } else {
        __nv_bfloat16* cp = (__nv_bfloat16*)Cout;
        #pragma unroll
        for (int mt = 0; mt < 2; mt++) {
            #pragma unroll
            for (int half = 0; half < 2; half++) {
                const int row = by * BM + wm * 32 + mt * 16 + r_in + half * 8;
                const long rb = (long)row * N + bx * BN;
                #pragma unroll
                for (int nt = 0; nt < 4; nt++) {
                    const int col = wn * 32 + nt * 8 + c_in;
                    uint32_t lo = __bfloat16_as_ushort(
                        __float2bfloat16_rn(acc[mt][nt][half * 2 + 0]));
                    uint32_t hi = __bfloat16_as_ushort(
                        __float2bfloat16_rn(acc[mt][nt][half * 2 + 1]));
                    *(uint32_t*)(cp + rb + col) = lo | (hi << 16);
                }
            }
        }
    }
}

// ---- host launcher ----------------------------------------------------------
extern "C" void kernel_launch(void* const* d_in, const int* in_sizes, int n_in,
                              void* d_out, int out_size) {
    const float* x      = (const float*)d_in[0];
    const float* y      = (const float*)d_in[1];
    const float* adj    = (const float*)d_in[2];
    const float* sumrow = (const float*)d_in[3];
    const float* W      = (const float*)d_in[4];
    const float* bias   = (const float*)d_in[5];
    float* out = (float*)d_out;

    __nv_bfloat16 *ybf, *adjbf, *wbf, *sup;
    cudaGetSymbolAddress((void**)&ybf,   g_ybf);
    cudaGetSymbolAddress((void**)&adjbf, g_adjbf);
    cudaGetSymbolAddress((void**)&wbf,   g_wbf);
    cudaGetSymbolAddress((void**)&sup,   g_sup);

    cudaFuncSetAttribute(gcn_mma_kernel,
                         cudaFuncAttributeMaxDynamicSharedMemorySize, SMEM_TOTAL);

    const int n4_big = 8 * 1024 * 1024 / 4;   // y / adj in float4 units
    const int n4_w   = 1024 * 1024 / 4;

    cudaStream_t s2;
    cudaEvent_t evFork, evJoin;
    cudaStreamCreateWithFlags(&s2, cudaStreamNonBlocking);
    cudaEventCreateWithFlags(&evFork, cudaEventDisableTiming);
    cudaEventCreateWithFlags(&evJoin, cudaEventDisableTiming);

    dim3 blk(NTHREADS);

    // stream 0: f32 -> bf16 for y + W (needed by GEMM1)
    cvt_pair_bf16<<<2048, 256>>>((const float4*)y, (uint2*)ybf, n4_big,
                                 (const float4*)W, (uint2*)wbf, n4_w);

    // fork: s2 converts adj while stream 0 runs GEMM1
    cudaEventRecord(evFork, 0);
    cudaStreamWaitEvent(s2, evFork, 0);
    cvt_pair_bf16<<<2048, 256, 0, s2>>>((const float4*)adj, (uint2*)adjbf, n4_big,
                                        nullptr, nullptr, 0);
    cudaEventRecord(evJoin, s2);

    // stream 0: GEMM1: support[8192,1024] (bf16) = y_bf16 @ W_bf16
    gcn_mma_kernel<<<dim3(1024 / BN, 8192 / BM, 1), blk, SMEM_TOTAL>>>(
        ybf, wbf, sup,
        8192, 1024, 1024,
        0, 0, 0,
        nullptr, nullptr, nullptr, 0);

    // join: GEMM2 needs adjbf from s2
    cudaStreamWaitEvent(0, evJoin, 0);

    // stream 0: GEMM2 (batched, fused epilogue)
    gcn_mma_kernel<<<dim3(1024 / BN, 1024 / BM, 8), blk, SMEM_TOTAL>>>(
        adjbf, sup, out,
        1024, 1024, 1024,
        1024L * 1024, 1024L * 1024, 1024L * 1024,
        sumrow, bias, x, 1);

    cudaStreamDestroy(s2);
    cudaEventDestroy(evFork);
    cudaEventDestroy(evJoin);
}

// round 13
// speedup vs baseline: 1.0158x; 1.0158x over previous
#include <cuda_runtime.h>
#include <cuda_bf16.h>
#include <cstdint>

// ============================================================================
// GCN fused layer via warp-level bf16 mma.sync (portable PTX; tcgen05 is
// rejected by the harness's .target sm_103 ptxas pass):
//   support = y @ W                      (GEMM1, 8192x1024x1024, bf16 out)
//   out     = relu(adj @ support / adj_sumrow + b + x)   (GEMM2, 8x 1024^3)
// R13: R10 256-thr GEMM core (R12's 512-thr falsified the occupancy theory:
//      tensor% flat at 40% -> HMMA-rate floor). cvt_adj on a LOW-PRIORITY
//      stream with a 512-CTA grid (kills wave-2 slot displacement on GEMM1);
//      cvt_yw at MLP=4.
// ============================================================================

__device__ __nv_bfloat16 g_ybf  [8u * 1024u * 1024u];
__device__ __nv_bfloat16 g_adjbf[8u * 1024u * 1024u];
__device__ __nv_bfloat16 g_wbf  [1024u * 1024u];
__device__ __nv_bfloat16 g_sup  [8u * 1024u * 1024u];

static __device__ __forceinline__ uint32_t smem_u32(const void* p) {
    uint32_t a;
    asm("{ .reg .u64 t; cvta.to.shared.u64 t, %1; cvt.u32.u64 %0, t; }"
        : "=r"(a) : "l"(p));
    return a;
}

// ---- tile geometry ----------------------------------------------------------
#define BM 128
#define BN 128
#define BK 64
#define NSTAGE 3
#define LDA_B 144    // A smem row stride bytes (64 bf16 = 128B + 16 pad)
#define LDB_B 272    // B smem row stride bytes (128 bf16 + 8 pad)
#define A_SM_BYTES (BM * LDA_B)                   // 18432
#define B_SM_BYTES (BK * LDB_B)                   // 17408
#define STAGE_BYTES (A_SM_BYTES + B_SM_BYTES)     // 35840
#define BIAS_OFF (NSTAGE * STAGE_BYTES)           // 107520
#define SMEM_TOTAL (BIAS_OFF + 512)               // 108032

// ---- PTX wrappers -----------------------------------------------------------
#define CP_ASYNC_16(saddr, gptr) \
    asm volatile("cp.async.cg.shared.global [%0], [%1], 16;" \
        :: "r"(saddr), "l"(gptr) : "memory")
#define CP_ASYNC_COMMIT() asm volatile("cp.async.commit_group;" ::: "memory")
#define CP_ASYNC_WAIT_1() asm volatile("cp.async.wait_group 1;" ::: "memory")
#define CP_ASYNC_WAIT_0() asm volatile("cp.async.wait_group 0;" ::: "memory")

#define LDMATRIX_X4(r0, r1, r2, r3, addr) \
    asm volatile("ldmatrix.sync.aligned.m8n8.x4.shared.b16 {%0,%1,%2,%3}, [%4];" \
        : "=r"(r0), "=r"(r1), "=r"(r2), "=r"(r3) : "r"(addr))
#define LDMATRIX_X4_T(r0, r1, r2, r3, addr) \
    asm volatile("ldmatrix.sync.aligned.m8n8.x4.trans.shared.b16 {%0,%1,%2,%3}, [%4];" \
        : "=r"(r0), "=r"(r1), "=r"(r2), "=r"(r3) : "r"(addr))

#define MMA_BF16(c, a0, a1, a2, a3, b0, b1) \
    asm volatile("mma.sync.aligned.m16n8k16.row.col.f32.bf16.bf16.f32 " \
        "{%0,%1,%2,%3}, {%4,%5,%6,%7}, {%8,%9}, {%0,%1,%2,%3};" \
        : "+f"((c)[0]), "+f"((c)[1]), "+f"((c)[2]), "+f"((c)[3]) \
        : "r"(a0), "r"(a1), "r"(a2), "r"(a3), "r"(b0), "r"(b1))

static __device__ __forceinline__ uint2 cvt4(float4 v) {
    uint32_t lo = (uint32_t)__bfloat16_as_ushort(__float2bfloat16_rn(v.x))
                | ((uint32_t)__bfloat16_as_ushort(__float2bfloat16_rn(v.y)) << 16);
    uint32_t hi = (uint32_t)__bfloat16_as_ushort(__float2bfloat16_rn(v.z))
                | ((uint32_t)__bfloat16_as_ushort(__float2bfloat16_rn(v.w)) << 16);
    return make_uint2(lo, hi);
}

// ---- f32 -> bf16 conversion for up to two tensors, MLP=4 --------------------
__global__ void cvt_pair_bf16(const float4* __restrict__ p0, uint2* __restrict__ o0, int n0,
                              const float4* __restrict__ p1, uint2* __restrict__ o1, int n1) {
    const int total = n0 + n1;
    const int stride = gridDim.x * blockDim.x;
    int i = blockIdx.x * blockDim.x + threadIdx.x;
    for (; i + 3 * stride < total; i += 4 * stride) {
        int idx[4];
        const float4* in[4];
        uint2* out[4];
        #pragma unroll
        for (int u = 0; u < 4; u++) {
            int id = i + u * stride;
            if (id < n0) { in[u] = p0; out[u] = o0; }
            else         { id -= n0;  in[u] = p1; out[u] = o1; }
            idx[u] = id;
        }
        float4 v0 = __ldcs(in[0] + idx[0]);
        float4 v1 = __ldcs(in[1] + idx[1]);
        float4 v2 = __ldcs(in[2] + idx[2]);
        float4 v3 = __ldcs(in[3] + idx[3]);
        __stcs(out[0] + idx[0], cvt4(v0));
        __stcs(out[1] + idx[1], cvt4(v1));
        __stcs(out[2] + idx[2], cvt4(v2));
        __stcs(out[3] + idx[3], cvt4(v3));
    }
    for (; i < total; i += stride) {
        int idx = i;
        const float4* in;
        uint2* out;
        if (idx < n0) { in = p0; out = o0; } else { idx -= n0; in = p1; out = o1; }
        __stcs(out + idx, cvt4(__ldcs(in + idx)));
    }
}

// ---- mma.sync GEMM kernel (exact R6/R10 configuration) ----------------------
// A: [M,K] bf16 row-major.  B: [K,N] bf16 row-major.
// 256 threads = 8 warps (2 M x 4 N), warp tile 64x32, mma m16n8k16, BK=64.
__global__ __launch_bounds__(256, 2)
void gcn_mma_kernel(
    const __nv_bfloat16* __restrict__ A,
    const __nv_bfloat16* __restrict__ B,
    void* __restrict__ Cout,
    int M, int N, int K,
    long strideA, long strideB, long strideC,
    const float* __restrict__ sumrow,
    const float* __restrict__ bias,
    const float* __restrict__ xres,
    int do_epi)
{
    extern __shared__ char smem[];
    const uint32_t sb = smem_u32(smem);
    const int tid = threadIdx.x;
    const int wid = tid >> 5;
    const int lane = tid & 31;
    const int bx = blockIdx.x, by = blockIdx.y, bz = blockIdx.z;

    A += (long)bz * strideA + (long)by * BM * K;
    B += (long)bz * strideB + (long)bx * BN;

    if (do_epi && tid < 128)
        ((float*)(smem + BIAS_OFF))[tid] = bias[bx * BN + tid];

    // ---- stage loader: cp.async 16B chunks ----------------------------------
    const int aRow0 = tid >> 3, aC16 = tid & 7;          // A: rows += c*32
    const int bRow0 = tid >> 4, bC16 = tid & 15;         // B: rows += c*16
    auto load_stage = [&](int s, int k0) {
        const uint32_t base = sb + s * STAGE_BYTES;
        #pragma unroll
        for (int c = 0; c < 4; c++) {
            const int row = aRow0 + c * 32;
            const __nv_bfloat16* g = A + (long)row * K + k0 + aC16 * 8;
            CP_ASYNC_16(base + row * LDA_B + aC16 * 16, g);
        }
        #pragma unroll
        for (int c = 0; c < 4; c++) {
            const int row = bRow0 + c * 16;
            const __nv_bfloat16* g = B + (long)(k0 + row) * N + bC16 * 8;
            CP_ASYNC_16(base + A_SM_BYTES + row * LDB_B + bC16 * 16, g);
        }
        CP_ASYNC_COMMIT();
    };

    const int wm = wid >> 2;       // 0..1  -> M offset wm*64
    const int wn = wid & 3;        // 0..3  -> N offset wn*32

    float acc[4][4][4];
    #pragma unroll
    for (int i = 0; i < 4; i++)
        #pragma unroll
        for (int j = 0; j < 4; j++)
            #pragma unroll
            for (int k = 0; k < 4; k++)
                acc[i][j][k] = 0.0f;

    const int a_row_in = lane & 15;
    const int a_koff = (lane >> 4) * 16;
    const int b_grp = lane >> 3, b_in = lane & 7;
    const int b_krow_in = (b_grp & 1) * 8 + b_in;
    const int b_noff = (b_grp >> 1) * 16;

    const int NIT = K / BK;

    // prime 2 stages of the 3-stage ring
    load_stage(0, 0);
    load_stage(1, BK);

    int cur = 0;
    for (int it = 0; it < NIT; ++it) {
        if (it + 1 < NIT) CP_ASYNC_WAIT_1(); else CP_ASYNC_WAIT_0();
        __syncthreads();

        if (it + 2 < NIT) {
            int nxt = cur + 2; if (nxt >= NSTAGE) nxt -= NSTAGE;
            load_stage(nxt, (it + 2) * BK);
        }

        const uint32_t base_a = sb + cur * STAGE_BYTES;
        const uint32_t base_b = base_a + A_SM_BYTES;

        #pragma unroll
        for (int kk = 0; kk < 4; kk++) {    // 4 x k16 phases per BK=64
            uint32_t af[4][4], bfr[2][4];
            #pragma unroll
            for (int mt = 0; mt < 4; mt++) {
                const int row = wm * 64 + mt * 16 + a_row_in;
                const uint32_t ad = base_a + row * LDA_B + kk * 32 + a_koff;
                LDMATRIX_X4(af[mt][0], af[mt][1], af[mt][2], af[mt][3], ad);
            }
            #pragma unroll
            for (int nb = 0; nb < 2; nb++) {
                const int krow = kk * 16 + b_krow_in;
                const uint32_t bd = base_b + krow * LDB_B
                                  + wn * 64 + nb * 32 + b_noff;
                LDMATRIX_X4_T(bfr[nb][0], bfr[nb][1], bfr[nb][2], bfr[nb][3], bd);
            }
            #pragma unroll
            for (int mt = 0; mt < 4; mt++) {
                #pragma unroll
                for (int nt = 0; nt < 4; nt++) {
                    MMA_BF16(acc[mt][nt],
                             af[mt][0], af[mt][1], af[mt][2], af[mt][3],
                             bfr[nt >> 1][(nt & 1) * 2],
                             bfr[nt >> 1][(nt & 1) * 2 + 1]);
                }
            }
        }

        if (++cur >= NSTAGE) cur = 0;
    }

    // ---- epilogue (plain loads/stores) --------------------------------------
    const int r_in = lane >> 2;
    const int c_in = (lane & 3) * 2;

    if (do_epi) {
        const float* bsm = (const float*)(smem + BIAS_OFF);
        #pragma unroll
        for (int mt = 0; mt < 4; mt++) {
            #pragma unroll
            for (int half = 0; half < 2; half++) {
                const int row = by * BM + wm * 64 + mt * 16 + r_in + half * 8;
                const float inv = 1.0f / sumrow[bz * M + row];
                const long rb = (long)bz * strideC + (long)row * N + bx * BN;
                #pragma unroll
                for (int nt = 0; nt < 4; nt++) {
                    const int col = wn * 32 + nt * 8 + c_in;
                    const float a0 = acc[mt][nt][half * 2 + 0];
                    const float a1 = acc[mt][nt][half * 2 + 1];
                    float2 xv = *(const float2*)(xres + rb + col);
                    float2 o;
                    o.x = fmaxf(a0 * inv + bsm[col + 0] + xv.x, 0.0f);
                    o.y = fmaxf(a1 * inv + bsm[col + 1] + xv.y, 0.0f);
                    *(float2*)((float*)Cout + rb + col) = o;
                }
            }
        }
    } else {
        __nv_bfloat16* cp = (__nv_bfloat16*)Cout;
        #pragma unroll
        for (int mt = 0; mt < 4; mt++) {
            #pragma unroll
            for (int half = 0; half < 2; half++) {
                const int row = by * BM + wm * 64 + mt * 16 + r_in + half * 8;
                const long rb = (long)row * N + bx * BN;
                #pragma unroll
                for (int nt = 0; nt < 4; nt++) {
                    const int col = wn * 32 + nt * 8 + c_in;
                    uint32_t lo = __bfloat16_as_ushort(
                        __float2bfloat16_rn(acc[mt][nt][half * 2 + 0]));
                    uint32_t hi = __bfloat16_as_ushort(
                        __float2bfloat16_rn(acc[mt][nt][half * 2 + 1]));
                    *(uint32_t*)(cp + rb + col) = lo | (hi << 16);
                }
            }
        }
    }
}

// ---- host launcher ----------------------------------------------------------
extern "C" void kernel_launch(void* const* d_in, const int* in_sizes, int n_in,
                              void* d_out, int out_size) {
    const float* x      = (const float*)d_in[0];
    const float* y      = (const float*)d_in[1];
    const float* adj    = (const float*)d_in[2];
    const float* sumrow = (const float*)d_in[3];
    const float* W      = (const float*)d_in[4];
    const float* bias   = (const float*)d_in[5];
    float* out = (float*)d_out;

    __nv_bfloat16 *ybf, *adjbf, *wbf, *sup;
    cudaGetSymbolAddress((void**)&ybf,   g_ybf);
    cudaGetSymbolAddress((void**)&adjbf, g_adjbf);
    cudaGetSymbolAddress((void**)&wbf,   g_wbf);
    cudaGetSymbolAddress((void**)&sup,   g_sup);

    cudaFuncSetAttribute(gcn_mma_kernel,
                         cudaFuncAttributeMaxDynamicSharedMemorySize, SMEM_TOTAL);

    const int n4_big = 8 * 1024 * 1024 / 4;   // y / adj in float4 units
    const int n4_w   = 1024 * 1024 / 4;

    // Low-priority side stream: cvt_adj CTAs must not displace GEMM1's
    // wave-2 CTAs in the work distributor.
    int prLeast = 0, prGreatest = 0;
    cudaDeviceGetStreamPriorityRange(&prLeast, &prGreatest);
    cudaStream_t s2;
    cudaEvent_t evFork, evJoin;
    cudaStreamCreateWithPriority(&s2, cudaStreamNonBlocking, prLeast);
    cudaEventCreateWithFlags(&evFork, cudaEventDisableTiming);
    cudaEventCreateWithFlags(&evJoin, cudaEventDisableTiming);

    dim3 blk(256);

    // stream 0: f32 -> bf16 for y + W (needed by GEMM1)
    cvt_pair_bf16<<<2048, 256>>>((const float4*)y, (uint2*)ybf, n4_big,
                                 (const float4*)W, (uint2*)wbf, n4_w);

    // fork: s2 (low prio, 512 CTAs) converts adj while stream 0 runs GEMM1
    cudaEventRecord(evFork, 0);
    cudaStreamWaitEvent(s2, evFork, 0);
    cvt_pair_bf16<<<512, 256, 0, s2>>>((const float4*)adj, (uint2*)adjbf, n4_big,
                                       nullptr, nullptr, 0);
    cudaEventRecord(evJoin, s2);

    // stream 0: GEMM1: support[8192,1024] (bf16) = y_bf16 @ W_bf16
    gcn_mma_kernel<<<dim3(1024 / BN, 8192 / BM, 1), blk, SMEM_TOTAL>>>(
        ybf, wbf, sup,
        8192, 1024, 1024,
        0, 0, 0,
        nullptr, nullptr, nullptr, 0);

    // join: GEMM2 needs adjbf from s2
    cudaStreamWaitEvent(0, evJoin, 0);

    // stream 0: GEMM2 (batched, fused epilogue)
    gcn_mma_kernel<<<dim3(1024 / BN, 1024 / BM, 8), blk, SMEM_TOTAL>>>(
        adjbf, sup, out,
        1024, 1024, 1024,
        1024L * 1024, 1024L * 1024, 1024L * 1024,
        sumrow, bias, x, 1);

    cudaStreamDestroy(s2);
    cudaEventDestroy(evFork);
    cudaEventDestroy(evJoin);
}